// round 6
// baseline (speedup 1.0000x reference)
#include <cuda_runtime.h>
#include <cfloat>

#define POOL 7
#define SCALE 0.0625f
#define CHANS 256
#define FH 224
#define FW 224
#define N_ROIS 512
#define MAX_STRIPS 8   // width <= we[6]-xs <= 226 -> ceil/32 = 8

// Replicate XLA-GPU's fp32 division (approximate, NOT correctly rounded).
// This exact op is what makes rel_err == 0 vs the reference. DO NOT CHANGE.
__device__ __forceinline__ float div_full(float a, float b) {
    float r; asm("div.full.f32 %0, %1, %2;" : "=f"(r) : "f"(a), "f"(b)); return r;
}
// round_half_up(v * 0.0625) — exact in fp32 for the input range
__device__ __forceinline__ int rhus(float v) {
    return (int)floorf(__fadd_rn(__fmul_rn(v, SCALE), 0.5f));
}

// One warp per (roi n, channel c). Lanes cover columns; a lane's pw-bin
// membership is column-invariant across rows -> single accumulator per strip.
__global__ void __launch_bounds__(128) roipool_warp_kernel(
    const float* __restrict__ feat,
    const float* __restrict__ rois,
    float* __restrict__ out)
{
    const int warp = threadIdx.x >> 5;
    const int lane = threadIdx.x & 31;
    const int c = blockIdx.x >> 7;                     // channel slowest -> L2-resident feat slice
    const int n = ((blockIdx.x & 127) << 2) + warp;    // 4 rois per block

    const float* roi = rois + n * 5;
    const int b  = (int)roi[0];
    const int xs = rhus(roi[1]);
    const int ys = rhus(roi[2]);
    const int xe = rhus(roi[3]);
    const int ye = rhus(roi[4]);
    const int roi_w = max(xe - xs + 1, 1);
    const int roi_h = max(ye - ys + 1, 1);
    const float bin_h = div_full((float)roi_h, 7.0f);
    const float bin_w = div_full((float)roi_w, 7.0f);

    // Clipped per-pw column ranges from the exact reference arithmetic
    int ws[POOL], we[POOL];
    int wvalid = 0;
    #pragma unroll
    for (int p = 0; p < POOL; ++p) {
        int a0 = min(max((int)floorf(__fmul_rn((float)p,       bin_w)) + xs, 0), FW);
        int a1 = min(max((int)ceilf (__fmul_rn((float)(p + 1), bin_w)) + xs, 0), FW);
        ws[p] = a0; we[p] = a1;
        if (a0 < a1) wvalid |= 1 << p;
    }

    // FIX (R6): the workspace end must come from the actual clipped bin
    // boundaries — due to div.full rounding, we[6] can be xs+roi_w+1.
    // we[] is monotonic nondecreasing, so we[POOL-1] is the max.
    const int wlimit  = we[POOL - 1];
    const int nstrips = max(0, (wlimit - xs + 31) >> 5);   // warp-uniform

    // Per-lane, per-strip: 7-bit membership mask (column-invariant!)
    int mask[MAX_STRIPS];
    #pragma unroll
    for (int s = 0; s < MAX_STRIPS; ++s) {
        int col = xs + (s << 5) + lane;
        int m = 0;
        if (s < nstrips && col < wlimit) {
            #pragma unroll
            for (int p = 0; p < POOL; ++p)
                if (col >= ws[p] && col < we[p]) m |= 1 << p;
        }
        mask[s] = m;
    }

    const float* fmap = feat + ((long long)b * CHANS + c) * (FH * FW);
    float* orow = out + ((n * CHANS + c) * POOL) * POOL;

    #pragma unroll
    for (int ph = 0; ph < POOL; ++ph) {
        const int hs = min(max((int)floorf(__fmul_rn((float)ph,       bin_h)) + ys, 0), FH);
        const int he = min(max((int)ceilf (__fmul_rn((float)(ph + 1), bin_h)) + ys, 0), FH);

        float acc[MAX_STRIPS];
        // Per-strip vertical max sweep: coalesced loads, 1 fmax per element.
        #pragma unroll
        for (int s = 0; s < MAX_STRIPS; ++s) {
            acc[s] = -FLT_MAX;
            if (s >= nstrips) break;                    // warp-uniform early exit
            const bool active = mask[s] != 0;           // lane predicate, hoisted
            const float* p0 = fmap + hs * FW + xs + (s << 5) + lane;
            float a = -FLT_MAX;
            for (int h = hs; h < he; ++h, p0 += FW) {
                if (active) a = fmaxf(a, __ldg(p0));
            }
            acc[s] = a;
        }

        const bool hv = hs < he;
        // Per-pw: select contributing strips, butterfly-reduce across lanes.
        #pragma unroll
        for (int p = 0; p < POOL; ++p) {
            float v = -FLT_MAX;
            #pragma unroll
            for (int s = 0; s < MAX_STRIPS; ++s)
                if ((mask[s] >> p) & 1) v = fmaxf(v, acc[s]);
            #pragma unroll
            for (int off = 16; off; off >>= 1)
                v = fmaxf(v, __shfl_xor_sync(0xffffffffu, v, off));
            if (lane == p)
                orow[ph * POOL + p] = (hv && ((wvalid >> p) & 1)) ? v : 0.0f;
        }
    }
}

extern "C" void kernel_launch(void* const* d_in, const int* in_sizes, int n_in,
                              void* d_out, int out_size) {
    const float* feat;
    const float* rois;
    if (in_sizes[0] > in_sizes[1]) {
        feat = (const float*)d_in[0];
        rois = (const float*)d_in[1];
    } else {
        feat = (const float*)d_in[1];
        rois = (const float*)d_in[0];
    }
    float* out = (float*)d_out;

    // 128 blocks per channel x 256 channels; 4 warps (=4 rois) per block
    int blocks = CHANS * (N_ROIS / 4);   // 32768
    roipool_warp_kernel<<<blocks, 128>>>(feat, rois, out);
}

// round 7
// speedup vs baseline: 4.3979x; 4.3979x over previous
#include <cuda_runtime.h>
#include <cfloat>

#define POOL 7
#define SCALE 0.0625f
#define CHANS 256
#define FH 224
#define FW 224
#define N_ROIS 512
#define S4 2   // max float4-strips: width <= 226 -> ceil(226/128) = 2

// Replicate XLA-GPU's fp32 division (approximate, NOT correctly rounded).
// This exact op is what makes rel_err == 0 vs the reference. DO NOT CHANGE.
__device__ __forceinline__ float div_full(float a, float b) {
    float r; asm("div.full.f32 %0, %1, %2;" : "=f"(r) : "f"(a), "f"(b)); return r;
}
// round_half_up(v * 0.0625) — exact in fp32 for the input range
__device__ __forceinline__ int rhus(float v) {
    return (int)floorf(__fadd_rn(__fmul_rn(v, SCALE), 0.5f));
}
__device__ __forceinline__ float4 fmax4(float4 a, float4 b) {
    return make_float4(fmaxf(a.x, b.x), fmaxf(a.y, b.y),
                       fmaxf(a.z, b.z), fmaxf(a.w, b.w));
}

// One warp per (roi, channel). Lane covers 4 consecutive columns (float4);
// strip = 128 columns, at most 2 strips. Column bin-membership is
// row-invariant -> one packed 28-bit mask per strip per lane.
__global__ void __launch_bounds__(128, 8) roipool_v4_kernel(
    const float* __restrict__ feat,
    const float* __restrict__ rois,
    float* __restrict__ out)
{
    const int warp = threadIdx.x >> 5;
    const int lane = threadIdx.x & 31;
    const int c = blockIdx.x >> 7;                   // channel slowest -> L2-resident slice
    const int n = ((blockIdx.x & 127) << 2) + warp;  // 4 rois per block

    const float* roi = rois + n * 5;
    const int b  = (int)roi[0];
    const int xs = rhus(roi[1]);
    const int ys = rhus(roi[2]);
    const int xe = rhus(roi[3]);
    const int ye = rhus(roi[4]);
    const int roi_w = max(xe - xs + 1, 1);
    const int roi_h = max(ye - ys + 1, 1);
    const float bin_h = div_full((float)roi_h, 7.0f);
    const float bin_w = div_full((float)roi_w, 7.0f);

    // Exact clipped per-pw column ranges (reference-identical arithmetic)
    int ws[POOL], we[POOL];
    int wvalid = 0;
    #pragma unroll
    for (int p = 0; p < POOL; ++p) {
        int a0 = min(max((int)floorf(__fmul_rn((float)p,       bin_w)) + xs, 0), FW);
        int a1 = min(max((int)ceilf (__fmul_rn((float)(p + 1), bin_w)) + xs, 0), FW);
        ws[p] = a0; we[p] = a1;
        if (a0 < a1) wvalid |= 1 << p;
    }
    const int wlimit = we[POOL - 1];           // max of clipped ends (monotone)
    const int xs4    = xs & ~3;                // 16B-aligned strip base
    const int ns4    = max(0, (wlimit - xs4 + 127) >> 7);  // 0..2 strips

    // Packed membership: bit (cc*7 + p) -> lane col (base+cc) is in bin p
    unsigned cmask[S4];
    #pragma unroll
    for (int s = 0; s < S4; ++s) {
        unsigned m = 0;
        int base = xs4 + (s << 7) + (lane << 2);
        #pragma unroll
        for (int cc = 0; cc < 4; ++cc) {
            int col = base + cc;
            #pragma unroll
            for (int p = 0; p < POOL; ++p)
                if (col >= ws[p] && col < we[p]) m |= 1u << (cc * 7 + p);
        }
        cmask[s] = m;
    }

    // Lane load predicates (start < wlimit ensures start <= 220 -> in-row)
    const bool pr0 = (ns4 > 0) && (xs4 + (lane << 2) < wlimit);
    const bool pr1 = (ns4 > 1) && (xs4 + 128 + (lane << 2) < wlimit);

    const float* fmap = feat + ((long long)b * CHANS + c) * (FH * FW);
    float* orow = out + ((n * CHANS + c) * POOL) * POOL;

    #pragma unroll
    for (int ph = 0; ph < POOL; ++ph) {
        const int hs = min(max((int)floorf(__fmul_rn((float)ph,       bin_h)) + ys, 0), FH);
        const int he = min(max((int)ceilf (__fmul_rn((float)(ph + 1), bin_h)) + ys, 0), FH);

        const float NEG = -FLT_MAX;
        float4 a00 = make_float4(NEG, NEG, NEG, NEG), a01 = a00;
        float4 a10 = a00, a11 = a00;

        const float* r = fmap + hs * FW + xs4 + (lane << 2);
        int h = hs;
        // 2-deep row unroll x up-to-2 strips: 4 independent LDG.128 in flight
        for (; h + 1 < he; h += 2, r += 2 * FW) {
            float4 v0, v1, w0, w1;
            if (pr0) { v0 = __ldg((const float4*)r);
                       v1 = __ldg((const float4*)(r + FW)); }
            if (pr1) { w0 = __ldg((const float4*)(r + 128));
                       w1 = __ldg((const float4*)(r + FW + 128)); }
            if (pr0) { a00 = fmax4(a00, v0); a01 = fmax4(a01, v1); }
            if (pr1) { a10 = fmax4(a10, w0); a11 = fmax4(a11, w1); }
        }
        if (h < he) {
            if (pr0) a00 = fmax4(a00, __ldg((const float4*)r));
            if (pr1) a10 = fmax4(a10, __ldg((const float4*)(r + 128)));
        }
        const float4 s0 = fmax4(a00, a01);
        const float4 s1 = fmax4(a10, a11);

        const bool hv = hs < he;
        #pragma unroll
        for (int p = 0; p < POOL; ++p) {
            float v = NEG;
            unsigned m0 = cmask[0] >> p;
            if (m0 & 1u)          v = fmaxf(v, s0.x);
            if ((m0 >> 7) & 1u)   v = fmaxf(v, s0.y);
            if ((m0 >> 14) & 1u)  v = fmaxf(v, s0.z);
            if ((m0 >> 21) & 1u)  v = fmaxf(v, s0.w);
            unsigned m1 = cmask[1] >> p;
            if (m1 & 1u)          v = fmaxf(v, s1.x);
            if ((m1 >> 7) & 1u)   v = fmaxf(v, s1.y);
            if ((m1 >> 14) & 1u)  v = fmaxf(v, s1.z);
            if ((m1 >> 21) & 1u)  v = fmaxf(v, s1.w);
            #pragma unroll
            for (int off = 16; off; off >>= 1)
                v = fmaxf(v, __shfl_xor_sync(0xffffffffu, v, off));
            if (lane == p)
                orow[ph * POOL + p] = (hv && ((wvalid >> p) & 1)) ? v : 0.0f;
        }
    }
}

extern "C" void kernel_launch(void* const* d_in, const int* in_sizes, int n_in,
                              void* d_out, int out_size) {
    const float* feat;
    const float* rois;
    if (in_sizes[0] > in_sizes[1]) {
        feat = (const float*)d_in[0];
        rois = (const float*)d_in[1];
    } else {
        feat = (const float*)d_in[1];
        rois = (const float*)d_in[0];
    }
    float* out = (float*)d_out;

    // 128 blocks per channel x 256 channels; 4 warps (=4 rois) per block
    int blocks = CHANS * (N_ROIS / 4);   // 32768
    roipool_v4_kernel<<<blocks, 128>>>(feat, rois, out);
}

// round 8
// speedup vs baseline: 11.5994x; 2.6375x over previous
#include <cuda_runtime.h>
#include <cfloat>

#define POOL 7
#define SCALE 0.0625f
#define CHANS 256
#define FH 224
#define FW 224
#define N_ROIS 512

// Replicate XLA-GPU's fp32 division (approximate, NOT correctly rounded).
// This exact op is what makes rel_err == 0 vs the reference. DO NOT CHANGE.
__device__ __forceinline__ float div_full(float a, float b) {
    float r; asm("div.full.f32 %0, %1, %2;" : "=f"(r) : "f"(a), "f"(b)); return r;
}
// round_half_up(v * 0.0625) — exact in fp32 for the input range
__device__ __forceinline__ int rhus(float v) {
    return (int)floorf(__fadd_rn(__fmul_rn(v, SCALE), 0.5f));
}
__device__ __forceinline__ float4 fmax4(float4 a, float4 b) {
    return make_float4(fmaxf(a.x, b.x), fmaxf(a.y, b.y),
                       fmaxf(a.z, b.z), fmaxf(a.w, b.w));
}

// One warp per (roi, channel). Lane covers 4 consecutive columns (float4);
// strip = 128 cols, at most 2 strips (width <= 224). Column maxes go to SMEM;
// lanes 0..6 then serially reduce their own bin's column range — no masks,
// no butterfly shuffles.
__global__ void __launch_bounds__(128, 10) roipool_v5_kernel(
    const float* __restrict__ feat,
    const float* __restrict__ rois,
    float* __restrict__ out)
{
    __shared__ float smf[4][256];
    const int warp = threadIdx.x >> 5;
    const int lane = threadIdx.x & 31;
    const int c = blockIdx.x >> 7;                   // channel slowest -> L2-resident slice
    const int n = ((blockIdx.x & 127) << 2) + warp;  // 4 rois per block

    const float* roi = rois + n * 5;
    const int b  = (int)roi[0];
    const int xs = rhus(roi[1]);
    const int ys = rhus(roi[2]);
    const int xe = rhus(roi[3]);
    const int ye = rhus(roi[4]);
    const int roi_w = max(xe - xs + 1, 1);
    const int roi_h = max(ye - ys + 1, 1);
    const float bin_h = div_full((float)roi_h, 7.0f);
    const float bin_w = div_full((float)roi_w, 7.0f);

    // Each lane p<7 owns pw-bin p: its exact clipped column range only.
    const float pf = (float)lane;
    const int wsp = min(max((int)floorf(__fmul_rn(pf,        bin_w)) + xs, 0), FW);
    const int wep = min(max((int)ceilf (__fmul_rn(pf + 1.0f, bin_w)) + xs, 0), FW);
    // Workspace end = lane 6's clipped bin end (monotone max; can exceed
    // xs+roi_w due to div.full rounding — load-bearing for bit-exactness).
    const int wlimit = __shfl_sync(0xffffffffu, wep, 6);
    const int xs4  = xs & ~3;                        // 16B-aligned base
    const int ns4  = max(0, (wlimit - xs4 + 127) >> 7);
    const bool two = ns4 > 1;
    const int col0 = xs4 + (lane << 2);
    const bool pr0 = (ns4 > 0) && (col0 < wlimit);   // start<wlimit<=224 -> in-row
    const bool pr1 = two && (col0 + 128 < wlimit);

    const float* fmap = feat + ((long long)b * CHANS + c) * (FH * FW);
    float* orow = out + ((n * CHANS + c) * POOL) * POOL;
    const float NEG = -FLT_MAX;

    for (int ph = 0; ph < POOL; ++ph) {
        const float phf = (float)ph;
        const int hs = min(max((int)floorf(__fmul_rn(phf,        bin_h)) + ys, 0), FH);
        const int he = min(max((int)ceilf (__fmul_rn(phf + 1.0f, bin_h)) + ys, 0), FH);

        float4 a0 = make_float4(NEG, NEG, NEG, NEG), a1 = a0, b0 = a0, b1 = a0;
        const float* r = fmap + hs * FW + col0;
        int h = hs;
        if (two) {   // warp-uniform branch: dual-strip path (rare)
            for (; h + 1 < he; h += 2, r += 2 * FW) {
                float4 v0, v1, w0, w1;
                if (pr0) { v0 = __ldg((const float4*)r);
                           v1 = __ldg((const float4*)(r + FW)); }
                if (pr1) { w0 = __ldg((const float4*)(r + 128));
                           w1 = __ldg((const float4*)(r + 128 + FW)); }
                if (pr0) { a0 = fmax4(a0, v0); a1 = fmax4(a1, v1); }
                if (pr1) { b0 = fmax4(b0, w0); b1 = fmax4(b1, w1); }
            }
            if (h < he) {
                if (pr0) a0 = fmax4(a0, __ldg((const float4*)r));
                if (pr1) b0 = fmax4(b0, __ldg((const float4*)(r + 128)));
            }
        } else {     // single-strip fast path (common)
            for (; h + 1 < he; h += 2, r += 2 * FW) {
                float4 v0, v1;
                if (pr0) { v0 = __ldg((const float4*)r);
                           v1 = __ldg((const float4*)(r + FW)); }
                if (pr0) { a0 = fmax4(a0, v0); a1 = fmax4(a1, v1); }
            }
            if (h < he && pr0) a0 = fmax4(a0, __ldg((const float4*)r));
        }
        a0 = fmax4(a0, a1);
        b0 = fmax4(b0, b1);

        __syncwarp();                       // protect prev iteration's reads
        ((float4*)smf[warp])[lane] = a0;    // cols [xs4 .. xs4+127]
        if (two) ((float4*)smf[warp])[32 + lane] = b0;  // cols [xs4+128 ..]
        __syncwarp();

        if (lane < POOL) {
            float v = NEG;
            for (int col = wsp; col < wep; ++col)
                v = fmaxf(v, smf[warp][col - xs4]);
            orow[ph * POOL + lane] = (hs < he && wsp < wep) ? v : 0.0f;
        }
    }
}

extern "C" void kernel_launch(void* const* d_in, const int* in_sizes, int n_in,
                              void* d_out, int out_size) {
    const float* feat;
    const float* rois;
    if (in_sizes[0] > in_sizes[1]) {
        feat = (const float*)d_in[0];
        rois = (const float*)d_in[1];
    } else {
        feat = (const float*)d_in[1];
        rois = (const float*)d_in[0];
    }
    float* out = (float*)d_out;

    // 128 blocks per channel x 256 channels; 4 warps (=4 rois) per block
    int blocks = CHANS * (N_ROIS / 4);   // 32768
    roipool_v5_kernel<<<blocks, 128>>>(feat, rois, out);
}

// round 9
// speedup vs baseline: 12.2859x; 1.0592x over previous
#include <cuda_runtime.h>
#include <cfloat>

#define POOL 7
#define SCALE 0.0625f
#define CHANS 256
#define FH 224
#define FW 224
#define N_ROIS 512

// Replicate XLA-GPU's fp32 division (approximate, NOT correctly rounded).
// This exact op is what makes rel_err == 0 vs the reference. DO NOT CHANGE.
__device__ __forceinline__ float div_full(float a, float b) {
    float r; asm("div.full.f32 %0, %1, %2;" : "=f"(r) : "f"(a), "f"(b)); return r;
}
// round_half_up(v * 0.0625) — exact in fp32 for the input range
__device__ __forceinline__ int rhus(float v) {
    return (int)floorf(__fadd_rn(__fmul_rn(v, SCALE), 0.5f));
}
__device__ __forceinline__ float4 fmax4(float4 a, float4 b) {
    return make_float4(fmaxf(a.x, b.x), fmaxf(a.y, b.y),
                       fmaxf(a.z, b.z), fmaxf(a.w, b.w));
}

// One warp per (roi, channel). Lane covers 4 consecutive columns (float4);
// strip = 128 cols, at most 2 strips. Column maxes go to SMEM; epilogue uses
// 4 lanes per pw-bin (all 7 bins reduced in parallel) + 2-step shfl reduce.
__global__ void __launch_bounds__(128, 10) roipool_v6_kernel(
    const float* __restrict__ feat,
    const float* __restrict__ rois,
    float* __restrict__ out)
{
    __shared__ float smf[4][256];
    const int warp = threadIdx.x >> 5;
    const int lane = threadIdx.x & 31;
    const int c = blockIdx.x >> 7;                   // channel slowest -> L2-resident slice
    const int n = ((blockIdx.x & 127) << 2) + warp;  // 4 rois per block

    const float* roi = rois + n * 5;
    const int b  = (int)roi[0];
    const int xs = rhus(roi[1]);
    const int ys = rhus(roi[2]);
    const int xe = rhus(roi[3]);
    const int ye = rhus(roi[4]);
    const int roi_w = max(xe - xs + 1, 1);
    const int roi_h = max(ye - ys + 1, 1);
    const float bin_h = div_full((float)roi_h, 7.0f);
    const float bin_w = div_full((float)roi_w, 7.0f);

    // Lane p (p<7) computes pw-bin p's exact clipped column range.
    const float pf = (float)lane;
    const int wsp = min(max((int)floorf(__fmul_rn(pf,        bin_w)) + xs, 0), FW);
    const int wep = min(max((int)ceilf (__fmul_rn(pf + 1.0f, bin_w)) + xs, 0), FW);
    // Workspace end = lane 6's clipped bin end (monotone max; can exceed
    // xs+roi_w due to div.full rounding — load-bearing for bit-exactness).
    const int wlimit = __shfl_sync(0xffffffffu, wep, 6);
    const int xs4  = xs & ~3;                        // 16B-aligned base
    const int ns4  = max(0, (wlimit - xs4 + 127) >> 7);
    const bool two = ns4 > 1;
    const int col0 = xs4 + (lane << 2);
    const bool pr0 = (ns4 > 0) && (col0 < wlimit);   // start<wlimit<=224 -> in-row
    const bool pr1 = two && (col0 + 128 < wlimit);

    // Epilogue assignment: 4 lanes per bin, p = lane>>2, j = lane&3.
    const int ep = lane >> 2;                        // 0..7 (7 -> idle)
    const int ej = lane & 3;
    const int es = __shfl_sync(0xffffffffu, wsp, ep & 7);
    const int ee = __shfl_sync(0xffffffffu, wep, ep & 7);
    const bool eact = (ep < POOL);
    const bool ewv  = eact && (es < ee);

    const float* fmap = feat + ((long long)b * CHANS + c) * (FH * FW);
    float* orow = out + ((n * CHANS + c) * POOL) * POOL;
    const float NEG = -FLT_MAX;

    for (int ph = 0; ph < POOL; ++ph) {
        const float phf = (float)ph;
        const int hs = min(max((int)floorf(__fmul_rn(phf,        bin_h)) + ys, 0), FH);
        const int he = min(max((int)ceilf (__fmul_rn(phf + 1.0f, bin_h)) + ys, 0), FH);

        float4 a0 = make_float4(NEG, NEG, NEG, NEG), a1 = a0, b0 = a0, b1 = a0;
        const float* r = fmap + hs * FW + col0;
        int h = hs;
        if (two) {   // dual-strip path (rare), 2-deep unroll
            for (; h + 1 < he; h += 2, r += 2 * FW) {
                float4 v0, v1, w0, w1;
                if (pr0) { v0 = __ldg((const float4*)r);
                           v1 = __ldg((const float4*)(r + FW)); }
                if (pr1) { w0 = __ldg((const float4*)(r + 128));
                           w1 = __ldg((const float4*)(r + 128 + FW)); }
                if (pr0) { a0 = fmax4(a0, v0); a1 = fmax4(a1, v1); }
                if (pr1) { b0 = fmax4(b0, w0); b1 = fmax4(b1, w1); }
            }
            if (h < he) {
                if (pr0) a0 = fmax4(a0, __ldg((const float4*)r));
                if (pr1) b0 = fmax4(b0, __ldg((const float4*)(r + 128)));
            }
        } else {     // single-strip fast path, 4-deep unroll (4 LDG in flight)
            for (; h + 3 < he; h += 4, r += 4 * FW) {
                float4 v0, v1, v2, v3;
                if (pr0) { v0 = __ldg((const float4*)r);
                           v1 = __ldg((const float4*)(r + FW));
                           v2 = __ldg((const float4*)(r + 2 * FW));
                           v3 = __ldg((const float4*)(r + 3 * FW)); }
                if (pr0) { a0 = fmax4(a0, v0); a1 = fmax4(a1, v1);
                           a0 = fmax4(a0, v2); a1 = fmax4(a1, v3); }
            }
            for (; h < he; ++h, r += FW)
                if (pr0) a0 = fmax4(a0, __ldg((const float4*)r));
        }
        a0 = fmax4(a0, a1);
        b0 = fmax4(b0, b1);

        __syncwarp();                       // protect prev iteration's reads
        ((float4*)smf[warp])[lane] = a0;    // cols [xs4 .. xs4+127]
        if (two) ((float4*)smf[warp])[32 + lane] = b0;  // cols [xs4+128 ..]
        __syncwarp();

        // Parallel epilogue: 4 lanes stride bin ep's columns by 4
        float v = NEG;
        if (eact) {
            for (int col = es + ej; col < ee; col += 4)
                v = fmaxf(v, smf[warp][col - xs4]);
        }
        v = fmaxf(v, __shfl_xor_sync(0xffffffffu, v, 1));
        v = fmaxf(v, __shfl_xor_sync(0xffffffffu, v, 2));
        if (eact && ej == 0)
            orow[ph * POOL + ep] = (hs < he && ewv) ? v : 0.0f;
    }
}

extern "C" void kernel_launch(void* const* d_in, const int* in_sizes, int n_in,
                              void* d_out, int out_size) {
    const float* feat;
    const float* rois;
    if (in_sizes[0] > in_sizes[1]) {
        feat = (const float*)d_in[0];
        rois = (const float*)d_in[1];
    } else {
        feat = (const float*)d_in[1];
        rois = (const float*)d_in[0];
    }
    float* out = (float*)d_out;

    // 128 blocks per channel x 256 channels; 4 warps (=4 rois) per block
    int blocks = CHANS * (N_ROIS / 4);   // 32768
    roipool_v6_kernel<<<blocks, 128>>>(feat, rois, out);
}